// round 7
// baseline (speedup 1.0000x reference)
#include <cuda_runtime.h>
#include <cuda_fp16.h>
#include <math.h>
#include <stdint.h>

// ---------------- problem constants ----------------
#define T_     2048
#define HID_   2560
#define H_     40
#define NOPE_  64
#define ROPE_  32
#define VDIM_  64
#define QLORA_ 768
#define KVLORA_ 256
#define DQK_   288          // KVLORA + ROPE
#define QDIM_  96           // NOPE + ROPE
#define EPS_   1e-5f
#define LOG2E_ 1.4426950408889634f

// ---------------- device scratch (no cudaMalloc allowed) -------------------
__device__ __half g_hH   [(size_t)T_ * HID_];
__device__ __half g_wqaT [(size_t)QLORA_ * HID_];
__device__ __half g_wqbT [(size_t)H_ * QDIM_ * QLORA_];
__device__ __half g_wkvaT[(size_t)DQK_ * HID_];
__device__ __half g_wkcT [(size_t)H_ * KVLORA_ * NOPE_];
__device__ __half g_wvcT [(size_t)H_ * VDIM_ * KVLORA_];
__device__ __half g_woT  [(size_t)HID_ * H_ * VDIM_];
__device__ float  g_qaF  [(size_t)T_ * QLORA_];
__device__ __half g_qaH  [(size_t)T_ * QLORA_];
__device__ __half g_qH   [(size_t)T_ * H_ * QDIM_];
__device__ float  g_latF [(size_t)T_ * DQK_];
__device__ __half g_kinH [(size_t)T_ * DQK_];
__device__ __half g_qinH [(size_t)T_ * H_ * DQK_];
__device__ __half g_olatH[(size_t)T_ * H_ * KVLORA_];
__device__ __half g_oH   [(size_t)T_ * H_ * VDIM_];

// ---------------- mma / ldmatrix / cp.async primitives ---------------------
__device__ __forceinline__ uint32_t cvta_s(const void* p) {
    return (uint32_t)__cvta_generic_to_shared(p);
}
__device__ __forceinline__ void ldsm_x4(uint32_t (&r)[4], uint32_t a) {
    asm volatile("ldmatrix.sync.aligned.m8n8.x4.shared.b16 {%0,%1,%2,%3}, [%4];"
        : "=r"(r[0]), "=r"(r[1]), "=r"(r[2]), "=r"(r[3]) : "r"(a));
}
__device__ __forceinline__ void ldsm_x4_t(uint32_t (&r)[4], uint32_t a) {
    asm volatile("ldmatrix.sync.aligned.m8n8.x4.trans.shared.b16 {%0,%1,%2,%3}, [%4];"
        : "=r"(r[0]), "=r"(r[1]), "=r"(r[2]), "=r"(r[3]) : "r"(a));
}
__device__ __forceinline__ void mma16816(float (&c)[4], const uint32_t (&a)[4],
                                         uint32_t b0, uint32_t b1) {
    asm volatile(
        "mma.sync.aligned.m16n8k16.row.col.f32.f16.f16.f32 "
        "{%0,%1,%2,%3}, {%4,%5,%6,%7}, {%8,%9}, {%0,%1,%2,%3};"
        : "+f"(c[0]), "+f"(c[1]), "+f"(c[2]), "+f"(c[3])
        : "r"(a[0]), "r"(a[1]), "r"(a[2]), "r"(a[3]), "r"(b0), "r"(b1));
}
__device__ __forceinline__ void cpa16(uint32_t dst, const void* src) {
    asm volatile("cp.async.cg.shared.global [%0], [%1], 16;"
                 :: "r"(dst), "l"(src) : "memory");
}
__device__ __forceinline__ void cpa16z(uint32_t dst, const void* src, int sz) {
    asm volatile("cp.async.cg.shared.global [%0], [%1], 16, %2;"
                 :: "r"(dst), "l"(src), "r"(sz) : "memory");
}
__device__ __forceinline__ void cpa_commit() {
    asm volatile("cp.async.commit_group;" ::: "memory");
}
__device__ __forceinline__ void cpa_wait0() {
    asm volatile("cp.async.wait_group 0;" ::: "memory");
}
__device__ __forceinline__ void stC(float* p, float v)  { *p = v; }
__device__ __forceinline__ void stC(__half* p, float v) { *p = __float2half(v); }

// ---------------- fp32 -> fp16 convert --------------------------------------
__global__ void f2h_kernel(const float* __restrict__ x, __half* __restrict__ y, int n4) {
    int i = blockIdx.x * blockDim.x + threadIdx.x;
    if (i < n4) {
        float4 v = ((const float4*)x)[i];
        ((__half2*)y)[2 * i]     = __floats2half2_rn(v.x, v.y);
        ((__half2*)y)[2 * i + 1] = __floats2half2_rn(v.z, v.w);
    }
}

// ---------------- transpose + convert: out[c][r] = (half)in[r][c] -----------
__global__ void t2h_kernel(const float* __restrict__ in, __half* __restrict__ out,
                           int R, int C, long sIn, long sOut) {
    in  += (long)blockIdx.z * sIn;
    out += (long)blockIdx.z * sOut;
    __shared__ float tile[32][33];
    int c0 = blockIdx.x * 32, r0 = blockIdx.y * 32;
    int tx = threadIdx.x, ty = threadIdx.y;
    #pragma unroll
    for (int i = 0; i < 32; i += 8)
        tile[ty + i][tx] = in[(long)(r0 + ty + i) * C + c0 + tx];
    __syncthreads();
    #pragma unroll
    for (int i = 0; i < 32; i += 8)
        out[(long)(c0 + ty + i) * R + r0 + tx] = __float2half(tile[tx][ty + i]);
}

// ---------------- generic HGEMM, cp.async 2-stage ---------------------------
// A row-major [M][K] (lda), B stored as [N][K] (ldb), C [M][N] (ldc, OutT).
// BM=128, BN=64, BK=32; 256 threads; M%128==0, K%32==0.
template <typename OutT>
__global__ __launch_bounds__(256)
void hgemm_kernel(const __half* __restrict__ A, const __half* __restrict__ B,
                  OutT* __restrict__ C,
                  int M, int N, int K, int lda, int ldb, int ldc,
                  long sA, long sB, long sC, float alpha)
{
    A += (long)blockIdx.z * sA;
    B += (long)blockIdx.z * sB;
    C += (long)blockIdx.z * sC;

    __shared__ __align__(16) __half As[2][128 * 40];
    __shared__ __align__(16) __half Bs[2][64 * 40];

    const int tid = threadIdx.x;
    const int lane = tid & 31, wid = tid >> 5;
    const int wm = wid & 3, wn = wid >> 2;
    const int m0 = blockIdx.y * 128, n0 = blockIdx.x * 64;

    float acc[2][4][4] = {};

    auto issue = [&](int st, int kt) {
        #pragma unroll
        for (int i = 0; i < 2; i++) {
            int id = tid + i * 256;
            int rr = id >> 2, cc = id & 3;
            cpa16(cvta_s(&As[st][rr * 40 + cc * 8]),
                  A + (long)(m0 + rr) * lda + kt * 32 + cc * 8);
        }
        {
            int rr = tid >> 2, cc = tid & 3;
            bool ok = (n0 + rr) < N;
            const __half* src = ok ? (B + (long)(n0 + rr) * ldb + kt * 32 + cc * 8) : B;
            cpa16z(cvta_s(&Bs[st][rr * 40 + cc * 8]), src, ok ? 16 : 0);
        }
        cpa_commit();
    };

    issue(0, 0);
    const int nk = K >> 5;
    for (int kt = 0; kt < nk; kt++) {
        const int cur = kt & 1;
        cpa_wait0();
        __syncthreads();
        if (kt + 1 < nk) issue(cur ^ 1, kt + 1);

        uint32_t aB = cvta_s(&As[cur][0]) +
                      ((wm * 32 + (lane & 15)) * 40 + ((lane >> 4) << 3)) * 2;
        uint32_t bB = cvta_s(&Bs[cur][0]) + ((wn * 32 + lane) * 40) * 2;
        #pragma unroll
        for (int ks = 0; ks < 2; ks++) {
            uint32_t Af0[4], Af1[4], B0[4], B1[4];
            ldsm_x4(Af0, aB + ks * 32);
            ldsm_x4(Af1, aB + ks * 32 + 16 * 40 * 2);
            ldsm_x4(B0, bB + ks * 32);
            ldsm_x4(B1, bB + ks * 32 + 16);
            #pragma unroll
            for (int nt = 0; nt < 4; nt++) {
                mma16816(acc[0][nt], Af0, B0[nt], B1[nt]);
                mma16816(acc[1][nt], Af1, B0[nt], B1[nt]);
            }
        }
    }

    #pragma unroll
    for (int mt = 0; mt < 2; mt++) {
        int r = m0 + wm * 32 + mt * 16 + (lane >> 2);
        #pragma unroll
        for (int nt = 0; nt < 4; nt++) {
            int c = n0 + wn * 32 + nt * 8 + (lane & 3) * 2;
            if (c < N) {
                stC(&C[(long)r * ldc + c],       alpha * acc[mt][nt][0]);
                stC(&C[(long)(r + 8) * ldc + c], alpha * acc[mt][nt][2]);
            }
            if (c + 1 < N) {
                stC(&C[(long)r * ldc + c + 1],       alpha * acc[mt][nt][1]);
                stC(&C[(long)(r + 8) * ldc + c + 1], alpha * acc[mt][nt][3]);
            }
        }
    }
}

// ---------------- RMSNorm (f32 in, OutT out) --------------------------------
template <typename OutT>
__global__ void rms_kernel(const float* __restrict__ x, const float* __restrict__ g,
                           OutT* __restrict__ y, int cols, int ldx, int ldy)
{
    long row = blockIdx.x;
    const float* xr = x + row * ldx;
    OutT*        yr = y + row * ldy;

    float ss = 0.f;
    for (int c = threadIdx.x; c < cols; c += blockDim.x) {
        float v = xr[c];
        ss = fmaf(v, v, ss);
    }
    #pragma unroll
    for (int o = 16; o; o >>= 1) ss += __shfl_xor_sync(0xffffffffu, ss, o);

    __shared__ float red[8];
    __shared__ float s_inv;
    int w = threadIdx.x >> 5;
    if ((threadIdx.x & 31) == 0) red[w] = ss;
    __syncthreads();
    if (threadIdx.x == 0) {
        float tot = 0.f;
        int nw = blockDim.x >> 5;
        for (int i = 0; i < nw; i++) tot += red[i];
        s_inv = rsqrtf(tot / (float)cols + EPS_);
    }
    __syncthreads();
    float inv = s_inv;
    for (int c = threadIdx.x; c < cols; c += blockDim.x)
        stC(&yr[c], xr[c] * inv * g[c]);
}

// ---------------- RoPE k: latF[:,256:288] -> kinH[:,256:288] ----------------
__global__ void rope_k_kernel(const int* __restrict__ pos,
                              const float* __restrict__ lat,
                              __half* __restrict__ kin)
{
    int t = blockIdx.x;
    int j = threadIdx.x;                  // 0..15
    float p = (float)pos[t];
    float inv_freq = powf(10000.f, -(float)j / 16.f);
    float f = p * inv_freq;
    float c = cosf(f), s = sinf(f);
    float x1 = lat[(long)t * DQK_ + KVLORA_ + j];
    float x2 = lat[(long)t * DQK_ + KVLORA_ + 16 + j];
    kin[(long)t * DQK_ + KVLORA_ + j]      = __float2half(x1 * c - x2 * s);
    kin[(long)t * DQK_ + KVLORA_ + 16 + j] = __float2half(x2 * c + x1 * s);
}

// ---------------- RoPE q (scaled): qH[:,h,64:96] -> qinH[:,h,256:288] -------
__global__ void rope_q_kernel(const int* __restrict__ pos,
                              const __half* __restrict__ q,
                              __half* __restrict__ qin, float scale)
{
    int t = blockIdx.x;
    int h = threadIdx.x >> 4;             // 0..39
    int j = threadIdx.x & 15;             // 0..15
    float p = (float)pos[t];
    float inv_freq = powf(10000.f, -(float)j / 16.f);
    float f = p * inv_freq;
    float c = cosf(f), s = sinf(f);
    long qb = (long)t * (H_ * QDIM_) + h * QDIM_ + NOPE_;
    float x1 = __half2float(q[qb + j]);
    float x2 = __half2float(q[qb + 16 + j]);
    long ob = (long)t * (H_ * DQK_) + h * DQK_ + KVLORA_;
    qin[ob + j]      = __float2half((x1 * c - x2 * s) * scale);
    qin[ob + 16 + j] = __float2half((x2 * c + x1 * s) * scale);
}

// ---------------- Flash attention (fp16 mma, register softmax) --------------
// Block: head h, 64 q rows. K tile 64x288 fp16 in smem; V = K[:, :256].
// 8 warps: S warp tile 16x32; PV warp tile 16x128. 2 CTAs/SM.
#define ATT_SMEM 86528

__global__ __launch_bounds__(256, 2)
void attn_kernel(const __half* __restrict__ qin, const __half* __restrict__ kin,
                 __half* __restrict__ olat)
{
    extern __shared__ __align__(16) char smraw[];
    __half* Qh   = (__half*)smraw;                  // 64 x 296       (37888 B)
    __half* Kh   = Qh + 64 * 296;                   // 64 x 296       (37888 B)
    __half* Ph   = (__half*)(smraw + 75776);        // 64 x 72        ( 9216 B)
    float*  mrow = (float*)(smraw + 84992);         // 64
    float*  lrow = (float*)(smraw + 85248);         // 64
    float*  pm   = (float*)(smraw + 85504);         // 2 x 64
    float*  ps   = (float*)(smraw + 86016);         // 2 x 64

    const int h    = blockIdx.y;
    const int qt   = (int)gridDim.x - 1 - (int)blockIdx.x;  // long work first
    const int tid  = threadIdx.x;
    const int lane = tid & 31, wid = tid >> 5;
    const int wm = wid & 3, wn = wid >> 2;
    const int r  = wm * 16 + (lane >> 2);           // tile row (and r+8)

    // async Q tile load: 64 rows x 288 halves, 16B chunks, 9 per thread
    {
        const __half* src = qin + ((long)(qt * 64) * H_ + h) * DQK_;
        #pragma unroll
        for (int i = 0; i < 9; i++) {
            int idx = tid + i * 256;
            int rr = idx / 36, cc = idx % 36;
            cpa16(cvta_s(&Qh[rr * 296 + cc * 8]),
                  src + (long)rr * (H_ * DQK_) + cc * 8);
        }
        cpa_commit();
    }
    if (tid < 64) { mrow[tid] = -INFINITY; lrow[tid] = 0.f; }

    float o[16][4];
    #pragma unroll
    for (int i = 0; i < 16; i++)
        #pragma unroll
        for (int j = 0; j < 4; j++) o[i][j] = 0.f;

    for (int kt = 0; kt <= qt; kt++) {
        __syncthreads();   // prior PV done with Kh/Ph; mrow/lrow init visible

        // async K tile load
        {
            const __half* src = kin + (long)(kt * 64) * DQK_;
            #pragma unroll
            for (int i = 0; i < 9; i++) {
                int idx = tid + i * 256;
                int rr = idx / 36, cc = idx % 36;
                cpa16(cvta_s(&Kh[rr * 296 + cc * 8]),
                      src + (long)rr * DQK_ + cc * 8);
            }
            cpa_commit();
        }
        cpa_wait0();
        __syncthreads();

        // ---- S = Q K^T  (warp: 16 rows x 32 cols) ----
        float s[4][4] = {};
        {
            uint32_t aB = cvta_s(Qh) +
                          ((wm * 16 + (lane & 15)) * 296 + ((lane >> 4) << 3)) * 2;
            uint32_t bB = cvta_s(Kh) + ((wn * 32 + lane) * 296) * 2;
            #pragma unroll
            for (int kk = 0; kk < 18; kk++) {
                uint32_t Af[4], B0[4], B1[4];
                ldsm_x4(Af, aB + kk * 32);
                ldsm_x4(B0, bB + kk * 32);
                ldsm_x4(B1, bB + kk * 32 + 16);
                #pragma unroll
                for (int nt = 0; nt < 4; nt++) mma16816(s[nt], Af, B0[nt], B1[nt]);
            }
        }

        // ---- causal mask (diagonal tile) in registers ----
        if (kt == qt) {
            int rg = r;                         // same-tile comparison
            int cg = wn * 32 + (lane & 3) * 2;
            #pragma unroll
            for (int nt = 0; nt < 4; nt++) {
                int c = cg + nt * 8;
                if (c     > rg)     s[nt][0] = -INFINITY;
                if (c + 1 > rg)     s[nt][1] = -INFINITY;
                if (c     > rg + 8) s[nt][2] = -INFINITY;
                if (c + 1 > rg + 8) s[nt][3] = -INFINITY;
            }
        }

        // ---- phase A: warp-local row max, publish partials ----
        float mx0 = -INFINITY, mx1 = -INFINITY;
        #pragma unroll
        for (int nt = 0; nt < 4; nt++) {
            mx0 = fmaxf(mx0, fmaxf(s[nt][0], s[nt][1]));
            mx1 = fmaxf(mx1, fmaxf(s[nt][2], s[nt][3]));
        }
        mx0 = fmaxf(mx0, __shfl_xor_sync(0xffffffffu, mx0, 1));
        mx0 = fmaxf(mx0, __shfl_xor_sync(0xffffffffu, mx0, 2));
        mx1 = fmaxf(mx1, __shfl_xor_sync(0xffffffffu, mx1, 1));
        mx1 = fmaxf(mx1, __shfl_xor_sync(0xffffffffu, mx1, 2));
        float mo0 = mrow[r], mo1 = mrow[r + 8];
        if ((lane & 3) == 0) {
            pm[wn * 64 + r]     = mx0;
            pm[wn * 64 + r + 8] = mx1;
        }
        __syncthreads();

        // ---- phase B: combined max, exp in regs, write P (half2), sums ----
        float mn0 = fmaxf(mo0, fmaxf(pm[r],     pm[64 + r]));
        float mn1 = fmaxf(mo1, fmaxf(pm[r + 8], pm[64 + r + 8]));
        float corr0 = exp2f((mo0 - mn0) * LOG2E_);
        float corr1 = exp2f((mo1 - mn1) * LOG2E_);
        float sum0 = 0.f, sum1 = 0.f;
        {
            int cb = wn * 32 + (lane & 3) * 2;
            #pragma unroll
            for (int nt = 0; nt < 4; nt++) {
                float p0 = exp2f((s[nt][0] - mn0) * LOG2E_);
                float p1 = exp2f((s[nt][1] - mn0) * LOG2E_);
                float p2 = exp2f((s[nt][2] - mn1) * LOG2E_);
                float p3 = exp2f((s[nt][3] - mn1) * LOG2E_);
                sum0 += p0 + p1;
                sum1 += p2 + p3;
                *(__half2*)&Ph[r * 72 + cb + nt * 8]       = __floats2half2_rn(p0, p1);
                *(__half2*)&Ph[(r + 8) * 72 + cb + nt * 8] = __floats2half2_rn(p2, p3);
            }
        }
        sum0 += __shfl_xor_sync(0xffffffffu, sum0, 1);
        sum0 += __shfl_xor_sync(0xffffffffu, sum0, 2);
        sum1 += __shfl_xor_sync(0xffffffffu, sum1, 1);
        sum1 += __shfl_xor_sync(0xffffffffu, sum1, 2);
        if ((lane & 3) == 0) {
            ps[wn * 64 + r]     = sum0;
            ps[wn * 64 + r + 8] = sum1;
            if (wn == 0) { mrow[r] = mn0; mrow[r + 8] = mn1; }
        }
        __syncthreads();

        // ---- PV: O = O*corr + P V  (V = Kh[:, :256] via ldmatrix.trans) ----
        if (wn == 0 && (lane & 3) == 0) {
            lrow[r]     = lrow[r]     * corr0 + ps[r]     + ps[64 + r];
            lrow[r + 8] = lrow[r + 8] * corr1 + ps[r + 8] + ps[64 + r + 8];
        }
        #pragma unroll
        for (int nt = 0; nt < 16; nt++) {
            o[nt][0] *= corr0; o[nt][1] *= corr0;
            o[nt][2] *= corr1; o[nt][3] *= corr1;
        }
        {
            uint32_t pB = cvta_s(Ph) +
                          ((wm * 16 + (lane & 15)) * 72 + ((lane >> 4) << 3)) * 2;
            uint32_t vB = cvta_s(Kh) +
                          ((lane & 15) * 296 + wn * 128 + ((lane >> 4) << 3)) * 2;
            #pragma unroll
            for (int ks = 0; ks < 4; ks++) {
                uint32_t Af[4];
                ldsm_x4(Af, pB + ks * 32);
                #pragma unroll
                for (int ntp = 0; ntp < 8; ntp++) {
                    uint32_t B[4];
                    ldsm_x4_t(B, vB + (ks * 16 * 296 + ntp * 16) * 2);
                    mma16816(o[2 * ntp],     Af, B[0], B[1]);
                    mma16816(o[2 * ntp + 1], Af, B[2], B[3]);
                }
            }
        }
    }

    __syncthreads();   // final lrow updates visible

    // epilogue: normalize by l and store fp16
    {
        float il0 = 1.f / lrow[r];
        float il1 = 1.f / lrow[r + 8];
        long t0 = (long)qt * 64 + r;
        __half* d0 = olat + (t0 * H_ + h) * KVLORA_;
        __half* d1 = olat + ((t0 + 8) * H_ + h) * KVLORA_;
        #pragma unroll
        for (int nt = 0; nt < 16; nt++) {
            int c = wn * 128 + nt * 8 + (lane & 3) * 2;
            *(__half2*)&d0[c] = __floats2half2_rn(o[nt][0] * il0, o[nt][1] * il0);
            *(__half2*)&d1[c] = __floats2half2_rn(o[nt][2] * il1, o[nt][3] * il1);
        }
    }
}

// ---------------- host launchers --------------------------------------------
template <typename OutT>
static void launch_hgemm(const __half* A, const __half* B, OutT* C,
                         int M, int N, int K, int lda, int ldb, int ldc,
                         int batch, long sA, long sB, long sC, float alpha)
{
    dim3 grid((N + 63) / 64, M / 128, batch);
    hgemm_kernel<OutT><<<grid, 256>>>(A, B, C, M, N, K, lda, ldb, ldc, sA, sB, sC, alpha);
}

extern "C" void kernel_launch(void* const* d_in, const int* in_sizes, int n_in,
                              void* d_out, int out_size)
{
    const int*   positions = (const int*)  d_in[0];
    const float* hidden    = (const float*)d_in[1];
    const float* w_qa      = (const float*)d_in[2];
    const float* gqa       = (const float*)d_in[3];
    const float* w_qb      = (const float*)d_in[4];
    const float* w_kva     = (const float*)d_in[5];
    const float* gkva      = (const float*)d_in[6];
    const float* w_kc      = (const float*)d_in[7];
    const float* w_vc      = (const float*)d_in[8];
    const float* w_o       = (const float*)d_in[9];
    float* out = (float*)d_out;

    __half *hH, *wqaT, *wqbT, *wkvaT, *wkcT, *wvcT, *woT;
    __half *qaH, *qH, *kinH, *qinH, *olatH, *oH;
    float *qaF, *latF;
    cudaGetSymbolAddress((void**)&hH,    g_hH);
    cudaGetSymbolAddress((void**)&wqaT,  g_wqaT);
    cudaGetSymbolAddress((void**)&wqbT,  g_wqbT);
    cudaGetSymbolAddress((void**)&wkvaT, g_wkvaT);
    cudaGetSymbolAddress((void**)&wkcT,  g_wkcT);
    cudaGetSymbolAddress((void**)&wvcT,  g_wvcT);
    cudaGetSymbolAddress((void**)&woT,   g_woT);
    cudaGetSymbolAddress((void**)&qaF,   g_qaF);
    cudaGetSymbolAddress((void**)&qaH,   g_qaH);
    cudaGetSymbolAddress((void**)&qH,    g_qH);
    cudaGetSymbolAddress((void**)&latF,  g_latF);
    cudaGetSymbolAddress((void**)&kinH,  g_kinH);
    cudaGetSymbolAddress((void**)&qinH,  g_qinH);
    cudaGetSymbolAddress((void**)&olatH, g_olatH);
    cudaGetSymbolAddress((void**)&oH,    g_oH);

    const float scale = 1.0f / sqrtf((float)(NOPE_ + ROPE_));

    // --- convert inputs / weights to fp16 (weights transposed to [N][K]) ---
    {
        int n4 = T_ * HID_ / 4;
        f2h_kernel<<<(n4 + 255) / 256, 256>>>(hidden, hH, n4);
    }
    dim3 tb(32, 8);
    t2h_kernel<<<dim3(QLORA_ / 32, HID_ / 32, 1), tb>>>(w_qa, wqaT, HID_, QLORA_, 0, 0);
    t2h_kernel<<<dim3(H_ * QDIM_ / 32, QLORA_ / 32, 1), tb>>>(w_qb, wqbT, QLORA_, H_ * QDIM_, 0, 0);
    t2h_kernel<<<dim3(DQK_ / 32, HID_ / 32, 1), tb>>>(w_kva, wkvaT, HID_, DQK_, 0, 0);
    t2h_kernel<<<dim3(HID_ / 32, H_ * VDIM_ / 32, 1), tb>>>(w_o, woT, H_ * VDIM_, HID_, 0, 0);
    t2h_kernel<<<dim3(KVLORA_ / 32, NOPE_ / 32, H_), tb>>>(w_kc, wkcT, NOPE_, KVLORA_,
                 (long)NOPE_ * KVLORA_, (long)NOPE_ * KVLORA_);
    t2h_kernel<<<dim3(VDIM_ / 32, KVLORA_ / 32, H_), tb>>>(w_vc, wvcT, KVLORA_, VDIM_,
                 (long)KVLORA_ * VDIM_, (long)KVLORA_ * VDIM_);

    // 1) qaF = hidden @ w_qa
    launch_hgemm<float>(hH, wqaT, qaF, T_, QLORA_, HID_, HID_, HID_, QLORA_, 1, 0, 0, 0, 1.f);
    // 2) qaH = rms(qaF)
    rms_kernel<__half><<<T_, 256>>>(qaF, gqa, qaH, QLORA_, QLORA_, QLORA_);
    // 3) qH = qaH @ w_qb
    launch_hgemm<__half>(qaH, wqbT, qH, T_, H_ * QDIM_, QLORA_, QLORA_, QLORA_, H_ * QDIM_, 1, 0, 0, 0, 1.f);
    // 4) latF = hidden @ w_kva
    launch_hgemm<float>(hH, wkvaT, latF, T_, DQK_, HID_, HID_, HID_, DQK_, 1, 0, 0, 0, 1.f);
    // 5) kinH[:, :256] = rms(latF[:, :256])
    rms_kernel<__half><<<T_, 256>>>(latF, gkva, kinH, KVLORA_, DQK_, DQK_);
    // 6) kinH[:, 256:288] = rope(latF[:, 256:288])
    rope_k_kernel<<<T_, 16>>>(positions, latF, kinH);
    // 7) qinH[:, h, :256] = scale * q_nope @ w_kc[h]   (batched)
    launch_hgemm<__half>(qH, wkcT, qinH, T_, KVLORA_, NOPE_,
                         H_ * QDIM_, NOPE_, H_ * DQK_,
                         H_, (long)QDIM_, (long)NOPE_ * KVLORA_, (long)DQK_, scale);
    // 8) qinH[:, h, 256:288] = scale * rope(q_pe)
    rope_q_kernel<<<T_, H_ * 16>>>(positions, qH, qinH, scale);
    // 9) flash attention -> olatH
    {
        cudaFuncSetAttribute(attn_kernel, cudaFuncAttributeMaxDynamicSharedMemorySize, ATT_SMEM);
        dim3 grid(T_ / 64, H_);
        attn_kernel<<<grid, 256, ATT_SMEM>>>(qinH, kinH, olatH);
    }
    // 10) oH[:, h*64:] = olatH[:, h, :] @ w_vc[h]   (batched)
    launch_hgemm<__half>(olatH, wvcT, oH, T_, VDIM_, KVLORA_,
                         H_ * KVLORA_, KVLORA_, H_ * VDIM_,
                         H_, (long)KVLORA_, (long)KVLORA_ * VDIM_, (long)VDIM_, 1.f);
    // 11) out = oH @ w_o
    launch_hgemm<float>(oH, woT, out, T_, HID_, H_ * VDIM_, H_ * VDIM_, H_ * VDIM_, HID_, 1, 0, 0, 0, 1.f);
}

// round 8
// speedup vs baseline: 1.0035x; 1.0035x over previous
#include <cuda_runtime.h>
#include <cuda_fp16.h>
#include <math.h>
#include <stdint.h>

// ---------------- problem constants ----------------
#define T_     2048
#define HID_   2560
#define H_     40
#define NOPE_  64
#define ROPE_  32
#define VDIM_  64
#define QLORA_ 768
#define KVLORA_ 256
#define DQK_   288          // KVLORA + ROPE
#define QDIM_  96           // NOPE + ROPE
#define EPS_   1e-5f
#define LOG2E_ 1.4426950408889634f

// ---------------- device scratch (no cudaMalloc allowed) -------------------
__device__ __half g_hH   [(size_t)T_ * HID_];
__device__ __half g_wqaT [(size_t)QLORA_ * HID_];
__device__ __half g_wqbT [(size_t)H_ * QDIM_ * QLORA_];
__device__ __half g_wkvaT[(size_t)DQK_ * HID_];
__device__ __half g_wkcT [(size_t)H_ * KVLORA_ * NOPE_];
__device__ __half g_wvcT [(size_t)H_ * VDIM_ * KVLORA_];
__device__ __half g_woT  [(size_t)HID_ * H_ * VDIM_];
__device__ float  g_qaF  [(size_t)T_ * QLORA_];
__device__ __half g_qaH  [(size_t)T_ * QLORA_];
__device__ __half g_qH   [(size_t)T_ * H_ * QDIM_];
__device__ float  g_latF [(size_t)T_ * DQK_];
__device__ __half g_kinH [(size_t)T_ * DQK_];
__device__ __half g_qinH [(size_t)T_ * H_ * DQK_];
__device__ __half g_olatH[(size_t)T_ * H_ * KVLORA_];
__device__ __half g_oH   [(size_t)T_ * H_ * VDIM_];

// ---------------- mma / ldmatrix / cp.async primitives ---------------------
__device__ __forceinline__ uint32_t cvta_s(const void* p) {
    return (uint32_t)__cvta_generic_to_shared(p);
}
__device__ __forceinline__ void ldsm_x4(uint32_t (&r)[4], uint32_t a) {
    asm volatile("ldmatrix.sync.aligned.m8n8.x4.shared.b16 {%0,%1,%2,%3}, [%4];"
        : "=r"(r[0]), "=r"(r[1]), "=r"(r[2]), "=r"(r[3]) : "r"(a));
}
__device__ __forceinline__ void ldsm_x4_t(uint32_t (&r)[4], uint32_t a) {
    asm volatile("ldmatrix.sync.aligned.m8n8.x4.trans.shared.b16 {%0,%1,%2,%3}, [%4];"
        : "=r"(r[0]), "=r"(r[1]), "=r"(r[2]), "=r"(r[3]) : "r"(a));
}
__device__ __forceinline__ void mma16816(float (&c)[4], const uint32_t (&a)[4],
                                         uint32_t b0, uint32_t b1) {
    asm volatile(
        "mma.sync.aligned.m16n8k16.row.col.f32.f16.f16.f32 "
        "{%0,%1,%2,%3}, {%4,%5,%6,%7}, {%8,%9}, {%0,%1,%2,%3};"
        : "+f"(c[0]), "+f"(c[1]), "+f"(c[2]), "+f"(c[3])
        : "r"(a[0]), "r"(a[1]), "r"(a[2]), "r"(a[3]), "r"(b0), "r"(b1));
}
__device__ __forceinline__ void cpa16(uint32_t dst, const void* src) {
    asm volatile("cp.async.cg.shared.global [%0], [%1], 16;"
                 :: "r"(dst), "l"(src) : "memory");
}
__device__ __forceinline__ void cpa16z(uint32_t dst, const void* src, int sz) {
    asm volatile("cp.async.cg.shared.global [%0], [%1], 16, %2;"
                 :: "r"(dst), "l"(src), "r"(sz) : "memory");
}
__device__ __forceinline__ void cpa_commit() {
    asm volatile("cp.async.commit_group;" ::: "memory");
}
__device__ __forceinline__ void cpa_wait0() {
    asm volatile("cp.async.wait_group 0;" ::: "memory");
}
__device__ __forceinline__ void stC(float* p, float v)  { *p = v; }
__device__ __forceinline__ void stC(__half* p, float v) { *p = __float2half(v); }

// ---------------- fp32 -> fp16 convert --------------------------------------
__global__ void f2h_kernel(const float* __restrict__ x, __half* __restrict__ y, int n4) {
    int i = blockIdx.x * blockDim.x + threadIdx.x;
    if (i < n4) {
        float4 v = ((const float4*)x)[i];
        ((__half2*)y)[2 * i]     = __floats2half2_rn(v.x, v.y);
        ((__half2*)y)[2 * i + 1] = __floats2half2_rn(v.z, v.w);
    }
}

// ---------------- transpose + convert: out[c][r] = (half)in[r][c] -----------
__global__ void t2h_kernel(const float* __restrict__ in, __half* __restrict__ out,
                           int R, int C, long sIn, long sOut) {
    in  += (long)blockIdx.z * sIn;
    out += (long)blockIdx.z * sOut;
    __shared__ float tile[32][33];
    int c0 = blockIdx.x * 32, r0 = blockIdx.y * 32;
    int tx = threadIdx.x, ty = threadIdx.y;
    #pragma unroll
    for (int i = 0; i < 32; i += 8)
        tile[ty + i][tx] = in[(long)(r0 + ty + i) * C + c0 + tx];
    __syncthreads();
    #pragma unroll
    for (int i = 0; i < 32; i += 8)
        out[(long)(c0 + ty + i) * R + r0 + tx] = __float2half(tile[tx][ty + i]);
}

// ---------------- generic HGEMM, cp.async 2-stage ---------------------------
// A row-major [M][K] (lda), B stored as [N][K] (ldb), C [M][N] (ldc, OutT).
// BM=128, BN=64, BK=32; 256 threads; M%128==0, K%32==0.
template <typename OutT>
__global__ __launch_bounds__(256)
void hgemm_kernel(const __half* __restrict__ A, const __half* __restrict__ B,
                  OutT* __restrict__ C,
                  int M, int N, int K, int lda, int ldb, int ldc,
                  long sA, long sB, long sC, float alpha)
{
    A += (long)blockIdx.z * sA;
    B += (long)blockIdx.z * sB;
    C += (long)blockIdx.z * sC;

    __shared__ __align__(16) __half As[2][128 * 40];
    __shared__ __align__(16) __half Bs[2][64 * 40];

    const int tid = threadIdx.x;
    const int lane = tid & 31, wid = tid >> 5;
    const int wm = wid & 3, wn = wid >> 2;
    const int m0 = blockIdx.y * 128, n0 = blockIdx.x * 64;

    float acc[2][4][4] = {};

    auto issue = [&](int st, int kt) {
        #pragma unroll
        for (int i = 0; i < 2; i++) {
            int id = tid + i * 256;
            int rr = id >> 2, cc = id & 3;
            cpa16(cvta_s(&As[st][rr * 40 + cc * 8]),
                  A + (long)(m0 + rr) * lda + kt * 32 + cc * 8);
        }
        {
            int rr = tid >> 2, cc = tid & 3;
            bool ok = (n0 + rr) < N;
            const __half* src = ok ? (B + (long)(n0 + rr) * ldb + kt * 32 + cc * 8) : B;
            cpa16z(cvta_s(&Bs[st][rr * 40 + cc * 8]), src, ok ? 16 : 0);
        }
        cpa_commit();
    };

    issue(0, 0);
    const int nk = K >> 5;
    for (int kt = 0; kt < nk; kt++) {
        const int cur = kt & 1;
        cpa_wait0();
        __syncthreads();
        if (kt + 1 < nk) issue(cur ^ 1, kt + 1);

        uint32_t aB = cvta_s(&As[cur][0]) +
                      ((wm * 32 + (lane & 15)) * 40 + ((lane >> 4) << 3)) * 2;
        uint32_t bB = cvta_s(&Bs[cur][0]) + ((wn * 32 + lane) * 40) * 2;
        #pragma unroll
        for (int ks = 0; ks < 2; ks++) {
            uint32_t Af0[4], Af1[4], B0[4], B1[4];
            ldsm_x4(Af0, aB + ks * 32);
            ldsm_x4(Af1, aB + ks * 32 + 16 * 40 * 2);
            ldsm_x4(B0, bB + ks * 32);
            ldsm_x4(B1, bB + ks * 32 + 16);
            #pragma unroll
            for (int nt = 0; nt < 4; nt++) {
                mma16816(acc[0][nt], Af0, B0[nt], B1[nt]);
                mma16816(acc[1][nt], Af1, B0[nt], B1[nt]);
            }
        }
    }

    #pragma unroll
    for (int mt = 0; mt < 2; mt++) {
        int r = m0 + wm * 32 + mt * 16 + (lane >> 2);
        #pragma unroll
        for (int nt = 0; nt < 4; nt++) {
            int c = n0 + wn * 32 + nt * 8 + (lane & 3) * 2;
            if (c < N) {
                stC(&C[(long)r * ldc + c],       alpha * acc[mt][nt][0]);
                stC(&C[(long)(r + 8) * ldc + c], alpha * acc[mt][nt][2]);
            }
            if (c + 1 < N) {
                stC(&C[(long)r * ldc + c + 1],       alpha * acc[mt][nt][1]);
                stC(&C[(long)(r + 8) * ldc + c + 1], alpha * acc[mt][nt][3]);
            }
        }
    }
}

// ---------------- RMSNorm (f32 in, OutT out) --------------------------------
template <typename OutT>
__global__ void rms_kernel(const float* __restrict__ x, const float* __restrict__ g,
                           OutT* __restrict__ y, int cols, int ldx, int ldy)
{
    long row = blockIdx.x;
    const float* xr = x + row * ldx;
    OutT*        yr = y + row * ldy;

    float ss = 0.f;
    for (int c = threadIdx.x; c < cols; c += blockDim.x) {
        float v = xr[c];
        ss = fmaf(v, v, ss);
    }
    #pragma unroll
    for (int o = 16; o; o >>= 1) ss += __shfl_xor_sync(0xffffffffu, ss, o);

    __shared__ float red[8];
    __shared__ float s_inv;
    int w = threadIdx.x >> 5;
    if ((threadIdx.x & 31) == 0) red[w] = ss;
    __syncthreads();
    if (threadIdx.x == 0) {
        float tot = 0.f;
        int nw = blockDim.x >> 5;
        for (int i = 0; i < nw; i++) tot += red[i];
        s_inv = rsqrtf(tot / (float)cols + EPS_);
    }
    __syncthreads();
    float inv = s_inv;
    for (int c = threadIdx.x; c < cols; c += blockDim.x)
        stC(&yr[c], xr[c] * inv * g[c]);
}

// ---------------- RoPE k: latF[:,256:288] -> kinH[:,256:288] ----------------
__global__ void rope_k_kernel(const int* __restrict__ pos,
                              const float* __restrict__ lat,
                              __half* __restrict__ kin)
{
    int t = blockIdx.x;
    int j = threadIdx.x;                  // 0..15
    float p = (float)pos[t];
    float inv_freq = powf(10000.f, -(float)j / 16.f);
    float f = p * inv_freq;
    float c = cosf(f), s = sinf(f);
    float x1 = lat[(long)t * DQK_ + KVLORA_ + j];
    float x2 = lat[(long)t * DQK_ + KVLORA_ + 16 + j];
    kin[(long)t * DQK_ + KVLORA_ + j]      = __float2half(x1 * c - x2 * s);
    kin[(long)t * DQK_ + KVLORA_ + 16 + j] = __float2half(x2 * c + x1 * s);
}

// ---------------- RoPE q (scaled): qH[:,h,64:96] -> qinH[:,h,256:288] -------
__global__ void rope_q_kernel(const int* __restrict__ pos,
                              const __half* __restrict__ q,
                              __half* __restrict__ qin, float scale)
{
    int t = blockIdx.x;
    int h = threadIdx.x >> 4;             // 0..39
    int j = threadIdx.x & 15;             // 0..15
    float p = (float)pos[t];
    float inv_freq = powf(10000.f, -(float)j / 16.f);
    float f = p * inv_freq;
    float c = cosf(f), s = sinf(f);
    long qb = (long)t * (H_ * QDIM_) + h * QDIM_ + NOPE_;
    float x1 = __half2float(q[qb + j]);
    float x2 = __half2float(q[qb + 16 + j]);
    long ob = (long)t * (H_ * DQK_) + h * DQK_ + KVLORA_;
    qin[ob + j]      = __float2half((x1 * c - x2 * s) * scale);
    qin[ob + 16 + j] = __float2half((x2 * c + x1 * s) * scale);
}

// ---------------- Flash attention (fp16 mma, register softmax) --------------
// Block: head h, 64 q rows. K tile 64x288 fp16 in smem; V = K[:, :256].
// 8 warps: S warp tile 16x32; PV warp tile 16x128. 2 CTAs/SM.
#define ATT_SMEM 86528

__global__ __launch_bounds__(256, 2)
void attn_kernel(const __half* __restrict__ qin, const __half* __restrict__ kin,
                 __half* __restrict__ olat)
{
    extern __shared__ __align__(16) char smraw[];
    __half* Qh   = (__half*)smraw;                  // 64 x 296       (37888 B)
    __half* Kh   = Qh + 64 * 296;                   // 64 x 296       (37888 B)
    __half* Ph   = (__half*)(smraw + 75776);        // 64 x 72        ( 9216 B)
    float*  mrow = (float*)(smraw + 84992);         // 64
    float*  lrow = (float*)(smraw + 85248);         // 64
    float*  pm   = (float*)(smraw + 85504);         // 2 x 64
    float*  ps   = (float*)(smraw + 86016);         // 2 x 64

    const int h    = blockIdx.y;
    const int qt   = (int)gridDim.x - 1 - (int)blockIdx.x;  // long work first
    const int tid  = threadIdx.x;
    const int lane = tid & 31, wid = tid >> 5;
    const int wm = wid & 3, wn = wid >> 2;
    const int r  = wm * 16 + (lane >> 2);           // tile row (and r+8)

    // async Q tile load: 64 rows x 288 halves, 16B chunks, 9 per thread
    {
        const __half* src = qin + ((long)(qt * 64) * H_ + h) * DQK_;
        #pragma unroll
        for (int i = 0; i < 9; i++) {
            int idx = tid + i * 256;
            int rr = idx / 36, cc = idx % 36;
            cpa16(cvta_s(&Qh[rr * 296 + cc * 8]),
                  src + (long)rr * (H_ * DQK_) + cc * 8);
        }
        cpa_commit();
    }
    if (tid < 64) { mrow[tid] = -INFINITY; lrow[tid] = 0.f; }

    float o[16][4];
    #pragma unroll
    for (int i = 0; i < 16; i++)
        #pragma unroll
        for (int j = 0; j < 4; j++) o[i][j] = 0.f;

    for (int kt = 0; kt <= qt; kt++) {
        __syncthreads();   // prior PV done with Kh/Ph; mrow/lrow init visible

        // async K tile load
        {
            const __half* src = kin + (long)(kt * 64) * DQK_;
            #pragma unroll
            for (int i = 0; i < 9; i++) {
                int idx = tid + i * 256;
                int rr = idx / 36, cc = idx % 36;
                cpa16(cvta_s(&Kh[rr * 296 + cc * 8]),
                      src + (long)rr * DQK_ + cc * 8);
            }
            cpa_commit();
        }
        cpa_wait0();
        __syncthreads();

        // ---- S = Q K^T  (warp: 16 rows x 32 cols) ----
        float s[4][4] = {};
        {
            uint32_t aB = cvta_s(Qh) +
                          ((wm * 16 + (lane & 15)) * 296 + ((lane >> 4) << 3)) * 2;
            uint32_t bB = cvta_s(Kh) + ((wn * 32 + lane) * 296) * 2;
            #pragma unroll
            for (int kk = 0; kk < 18; kk++) {
                uint32_t Af[4], B0[4], B1[4];
                ldsm_x4(Af, aB + kk * 32);
                ldsm_x4(B0, bB + kk * 32);
                ldsm_x4(B1, bB + kk * 32 + 16);
                #pragma unroll
                for (int nt = 0; nt < 4; nt++) mma16816(s[nt], Af, B0[nt], B1[nt]);
            }
        }

        // ---- causal mask (diagonal tile) in registers ----
        if (kt == qt) {
            int rg = r;                         // same-tile comparison
            int cg = wn * 32 + (lane & 3) * 2;
            #pragma unroll
            for (int nt = 0; nt < 4; nt++) {
                int c = cg + nt * 8;
                if (c     > rg)     s[nt][0] = -INFINITY;
                if (c + 1 > rg)     s[nt][1] = -INFINITY;
                if (c     > rg + 8) s[nt][2] = -INFINITY;
                if (c + 1 > rg + 8) s[nt][3] = -INFINITY;
            }
        }

        // ---- phase A: warp-local row max, publish partials ----
        float mx0 = -INFINITY, mx1 = -INFINITY;
        #pragma unroll
        for (int nt = 0; nt < 4; nt++) {
            mx0 = fmaxf(mx0, fmaxf(s[nt][0], s[nt][1]));
            mx1 = fmaxf(mx1, fmaxf(s[nt][2], s[nt][3]));
        }
        mx0 = fmaxf(mx0, __shfl_xor_sync(0xffffffffu, mx0, 1));
        mx0 = fmaxf(mx0, __shfl_xor_sync(0xffffffffu, mx0, 2));
        mx1 = fmaxf(mx1, __shfl_xor_sync(0xffffffffu, mx1, 1));
        mx1 = fmaxf(mx1, __shfl_xor_sync(0xffffffffu, mx1, 2));
        float mo0 = mrow[r], mo1 = mrow[r + 8];
        if ((lane & 3) == 0) {
            pm[wn * 64 + r]     = mx0;
            pm[wn * 64 + r + 8] = mx1;
        }
        __syncthreads();

        // ---- phase B: combined max, exp in regs, write P (half2), sums ----
        float mn0 = fmaxf(mo0, fmaxf(pm[r],     pm[64 + r]));
        float mn1 = fmaxf(mo1, fmaxf(pm[r + 8], pm[64 + r + 8]));
        float corr0 = exp2f((mo0 - mn0) * LOG2E_);
        float corr1 = exp2f((mo1 - mn1) * LOG2E_);
        float sum0 = 0.f, sum1 = 0.f;
        {
            int cb = wn * 32 + (lane & 3) * 2;
            #pragma unroll
            for (int nt = 0; nt < 4; nt++) {
                float p0 = exp2f((s[nt][0] - mn0) * LOG2E_);
                float p1 = exp2f((s[nt][1] - mn0) * LOG2E_);
                float p2 = exp2f((s[nt][2] - mn1) * LOG2E_);
                float p3 = exp2f((s[nt][3] - mn1) * LOG2E_);
                sum0 += p0 + p1;
                sum1 += p2 + p3;
                *(__half2*)&Ph[r * 72 + cb + nt * 8]       = __floats2half2_rn(p0, p1);
                *(__half2*)&Ph[(r + 8) * 72 + cb + nt * 8] = __floats2half2_rn(p2, p3);
            }
        }
        sum0 += __shfl_xor_sync(0xffffffffu, sum0, 1);
        sum0 += __shfl_xor_sync(0xffffffffu, sum0, 2);
        sum1 += __shfl_xor_sync(0xffffffffu, sum1, 1);
        sum1 += __shfl_xor_sync(0xffffffffu, sum1, 2);
        if ((lane & 3) == 0) {
            ps[wn * 64 + r]     = sum0;
            ps[wn * 64 + r + 8] = sum1;
            if (wn == 0) { mrow[r] = mn0; mrow[r + 8] = mn1; }
        }
        __syncthreads();

        // ---- PV: O = O*corr + P V  (V = Kh[:, :256] via ldmatrix.trans) ----
        if (wn == 0 && (lane & 3) == 0) {
            lrow[r]     = lrow[r]     * corr0 + ps[r]     + ps[64 + r];
            lrow[r + 8] = lrow[r + 8] * corr1 + ps[r + 8] + ps[64 + r + 8];
        }
        #pragma unroll
        for (int nt = 0; nt < 16; nt++) {
            o[nt][0] *= corr0; o[nt][1] *= corr0;
            o[nt][2] *= corr1; o[nt][3] *= corr1;
        }
        {
            uint32_t pB = cvta_s(Ph) +
                          ((wm * 16 + (lane & 15)) * 72 + ((lane >> 4) << 3)) * 2;
            uint32_t vB = cvta_s(Kh) +
                          ((lane & 15) * 296 + wn * 128 + ((lane >> 4) << 3)) * 2;
            #pragma unroll
            for (int ks = 0; ks < 4; ks++) {
                uint32_t Af[4];
                ldsm_x4(Af, pB + ks * 32);
                #pragma unroll
                for (int ntp = 0; ntp < 8; ntp++) {
                    uint32_t B[4];
                    ldsm_x4_t(B, vB + (ks * 16 * 296 + ntp * 16) * 2);
                    mma16816(o[2 * ntp],     Af, B[0], B[1]);
                    mma16816(o[2 * ntp + 1], Af, B[2], B[3]);
                }
            }
        }
    }

    __syncthreads();   // final lrow updates visible

    // epilogue: normalize by l and store fp16
    {
        float il0 = 1.f / lrow[r];
        float il1 = 1.f / lrow[r + 8];
        long t0 = (long)qt * 64 + r;
        __half* d0 = olat + (t0 * H_ + h) * KVLORA_;
        __half* d1 = olat + ((t0 + 8) * H_ + h) * KVLORA_;
        #pragma unroll
        for (int nt = 0; nt < 16; nt++) {
            int c = wn * 128 + nt * 8 + (lane & 3) * 2;
            *(__half2*)&d0[c] = __floats2half2_rn(o[nt][0] * il0, o[nt][1] * il0);
            *(__half2*)&d1[c] = __floats2half2_rn(o[nt][2] * il1, o[nt][3] * il1);
        }
    }
}

// ---------------- host launchers --------------------------------------------
template <typename OutT>
static void launch_hgemm(const __half* A, const __half* B, OutT* C,
                         int M, int N, int K, int lda, int ldb, int ldc,
                         int batch, long sA, long sB, long sC, float alpha)
{
    dim3 grid((N + 63) / 64, M / 128, batch);
    hgemm_kernel<OutT><<<grid, 256>>>(A, B, C, M, N, K, lda, ldb, ldc, sA, sB, sC, alpha);
}

extern "C" void kernel_launch(void* const* d_in, const int* in_sizes, int n_in,
                              void* d_out, int out_size)
{
    const int*   positions = (const int*)  d_in[0];
    const float* hidden    = (const float*)d_in[1];
    const float* w_qa      = (const float*)d_in[2];
    const float* gqa       = (const float*)d_in[3];
    const float* w_qb      = (const float*)d_in[4];
    const float* w_kva     = (const float*)d_in[5];
    const float* gkva      = (const float*)d_in[6];
    const float* w_kc      = (const float*)d_in[7];
    const float* w_vc      = (const float*)d_in[8];
    const float* w_o       = (const float*)d_in[9];
    float* out = (float*)d_out;

    __half *hH, *wqaT, *wqbT, *wkvaT, *wkcT, *wvcT, *woT;
    __half *qaH, *qH, *kinH, *qinH, *olatH, *oH;
    float *qaF, *latF;
    cudaGetSymbolAddress((void**)&hH,    g_hH);
    cudaGetSymbolAddress((void**)&wqaT,  g_wqaT);
    cudaGetSymbolAddress((void**)&wqbT,  g_wqbT);
    cudaGetSymbolAddress((void**)&wkvaT, g_wkvaT);
    cudaGetSymbolAddress((void**)&wkcT,  g_wkcT);
    cudaGetSymbolAddress((void**)&wvcT,  g_wvcT);
    cudaGetSymbolAddress((void**)&woT,   g_woT);
    cudaGetSymbolAddress((void**)&qaF,   g_qaF);
    cudaGetSymbolAddress((void**)&qaH,   g_qaH);
    cudaGetSymbolAddress((void**)&qH,    g_qH);
    cudaGetSymbolAddress((void**)&latF,  g_latF);
    cudaGetSymbolAddress((void**)&kinH,  g_kinH);
    cudaGetSymbolAddress((void**)&qinH,  g_qinH);
    cudaGetSymbolAddress((void**)&olatH, g_olatH);
    cudaGetSymbolAddress((void**)&oH,    g_oH);

    const float scale = 1.0f / sqrtf((float)(NOPE_ + ROPE_));

    // --- convert inputs / weights to fp16 (weights transposed to [N][K]) ---
    {
        int n4 = T_ * HID_ / 4;
        f2h_kernel<<<(n4 + 255) / 256, 256>>>(hidden, hH, n4);
    }
    dim3 tb(32, 8);
    t2h_kernel<<<dim3(QLORA_ / 32, HID_ / 32, 1), tb>>>(w_qa, wqaT, HID_, QLORA_, 0, 0);
    t2h_kernel<<<dim3(H_ * QDIM_ / 32, QLORA_ / 32, 1), tb>>>(w_qb, wqbT, QLORA_, H_ * QDIM_, 0, 0);
    t2h_kernel<<<dim3(DQK_ / 32, HID_ / 32, 1), tb>>>(w_kva, wkvaT, HID_, DQK_, 0, 0);
    t2h_kernel<<<dim3(HID_ / 32, H_ * VDIM_ / 32, 1), tb>>>(w_o, woT, H_ * VDIM_, HID_, 0, 0);
    t2h_kernel<<<dim3(KVLORA_ / 32, NOPE_ / 32, H_), tb>>>(w_kc, wkcT, NOPE_, KVLORA_,
                 (long)NOPE_ * KVLORA_, (long)NOPE_ * KVLORA_);
    t2h_kernel<<<dim3(VDIM_ / 32, KVLORA_ / 32, H_), tb>>>(w_vc, wvcT, KVLORA_, VDIM_,
                 (long)KVLORA_ * VDIM_, (long)KVLORA_ * VDIM_);

    // 1) qaF = hidden @ w_qa
    launch_hgemm<float>(hH, wqaT, qaF, T_, QLORA_, HID_, HID_, HID_, QLORA_, 1, 0, 0, 0, 1.f);
    // 2) qaH = rms(qaF)
    rms_kernel<__half><<<T_, 256>>>(qaF, gqa, qaH, QLORA_, QLORA_, QLORA_);
    // 3) qH = qaH @ w_qb
    launch_hgemm<__half>(qaH, wqbT, qH, T_, H_ * QDIM_, QLORA_, QLORA_, QLORA_, H_ * QDIM_, 1, 0, 0, 0, 1.f);
    // 4) latF = hidden @ w_kva
    launch_hgemm<float>(hH, wkvaT, latF, T_, DQK_, HID_, HID_, HID_, DQK_, 1, 0, 0, 0, 1.f);
    // 5) kinH[:, :256] = rms(latF[:, :256])
    rms_kernel<__half><<<T_, 256>>>(latF, gkva, kinH, KVLORA_, DQK_, DQK_);
    // 6) kinH[:, 256:288] = rope(latF[:, 256:288])
    rope_k_kernel<<<T_, 16>>>(positions, latF, kinH);
    // 7) qinH[:, h, :256] = scale * q_nope @ w_kc[h]   (batched)
    launch_hgemm<__half>(qH, wkcT, qinH, T_, KVLORA_, NOPE_,
                         H_ * QDIM_, NOPE_, H_ * DQK_,
                         H_, (long)QDIM_, (long)NOPE_ * KVLORA_, (long)DQK_, scale);
    // 8) qinH[:, h, 256:288] = scale * rope(q_pe)
    rope_q_kernel<<<T_, H_ * 16>>>(positions, qH, qinH, scale);
    // 9) flash attention -> olatH
    {
        cudaFuncSetAttribute(attn_kernel, cudaFuncAttributeMaxDynamicSharedMemorySize, ATT_SMEM);
        dim3 grid(T_ / 64, H_);
        attn_kernel<<<grid, 256, ATT_SMEM>>>(qinH, kinH, olatH);
    }
    // 10) oH[:, h*64:] = olatH[:, h, :] @ w_vc[h]   (batched)
    launch_hgemm<__half>(olatH, wvcT, oH, T_, VDIM_, KVLORA_,
                         H_ * KVLORA_, KVLORA_, H_ * VDIM_,
                         H_, (long)KVLORA_, (long)KVLORA_ * VDIM_, (long)VDIM_, 1.f);
    // 11) out = oH @ w_o
    launch_hgemm<float>(oH, woT, out, T_, HID_, H_ * VDIM_, H_ * VDIM_, H_ * VDIM_, HID_, 1, 0, 0, 0, 1.f);
}